// round 3
// baseline (speedup 1.0000x reference)
#include <cuda_runtime.h>
#include <math.h>

// MoE FFN: B=4,S=2048 -> T=8192 tokens, D=1024, F=4096, E=8, top-2 routing.
// Inputs (metadata order): x[T,D] f32, W_gate[E,D] f32, Wg[E,F,D] f32,
// Wu[E,F,D] f32, Wd[E,D,F] f32. Output: [T,D] f32.

#define NT 8192
#define DD 1024
#define FF 4096
#define NE 8

#define BM 64
#define BN 64
#define BK 16

// -------- scratch (__device__ globals; no runtime allocation allowed) -------
__device__ int   g_count[NE];
__device__ int   g_pairs[NE][NT];   // pair = token*2 + k   (k = rank in top-2)
__device__ float g_wts[NE][NT];     // renormalized routing weight
__device__ float g_h[(size_t)NT * 2 * FF];   // 16384 x 4096 f32 = 256 MiB

// ---------------------------------------------------------------------------
__global__ void zero_counts_kernel() {
    if (threadIdx.x < NE) g_count[threadIdx.x] = 0;
}

// One warp per token: 8 router dot products, top-2, scatter to expert lists.
__global__ void router_kernel(const float* __restrict__ x,
                              const float* __restrict__ Wgate) {
    int warp = (blockIdx.x * blockDim.x + threadIdx.x) >> 5;
    int lane = threadIdx.x & 31;
    if (warp >= NT) return;
    const float* xr = x + (size_t)warp * DD;

    float lg[NE];
#pragma unroll
    for (int e = 0; e < NE; e++) {
        const float* w = Wgate + e * DD;
        float acc = 0.f;
#pragma unroll 8
        for (int i = lane; i < DD; i += 32) acc = fmaf(xr[i], w[i], acc);
#pragma unroll
        for (int o = 16; o; o >>= 1) acc += __shfl_xor_sync(0xffffffffu, acc, o);
        lg[e] = acc;
    }
    if (lane == 0) {
        // top-2 by logit (softmax is monotone); ties keep lowest index (jax top_k)
        int e0 = 0;
#pragma unroll
        for (int e = 1; e < NE; e++) if (lg[e] > lg[e0]) e0 = e;
        int e1 = (e0 == 0) ? 1 : 0;
#pragma unroll
        for (int e = 0; e < NE; e++) {
            if (e == e0 || e == e1) continue;
            if (lg[e] > lg[e1]) e1 = e;
        }
        // renormalized top-2 weights == softmax over {lg[e0], lg[e1]}
        float w0 = 1.f / (1.f + expf(lg[e1] - lg[e0]));
        float w1 = 1.f - w0;
        int p0 = atomicAdd(&g_count[e0], 1);
        g_pairs[e0][p0] = warp * 2;     g_wts[e0][p0] = w0;
        int p1 = atomicAdd(&g_count[e1], 1);
        g_pairs[e1][p1] = warp * 2 + 1; g_wts[e1][p1] = w1;
    }
}

// ---------------------------------------------------------------------------
// Kernel: gathered (gate, up) GEMM + silu fusion.
// C tile: BM tokens x BN f-columns; A shared between the two weight GEMMs.
__global__ __launch_bounds__(256, 2) void ffn1_kernel(
    const float* __restrict__ x,
    const float* __restrict__ Wg,
    const float* __restrict__ Wu) {
    const int e   = blockIdx.z;
    const int cnt = g_count[e];
    const int m0  = blockIdx.y * BM;
    if (m0 >= cnt) return;
    const int n0  = blockIdx.x * BN;

    __shared__ float As[BK][BM];
    __shared__ float Bgs[BK][BN];
    __shared__ float Bus[BK][BN];
    __shared__ int   sp[BM];

    const int tid = threadIdx.x;
    if (tid < BM) {
        int s = m0 + tid;
        sp[tid] = (s < cnt) ? g_pairs[e][s] : -1;
    }
    __syncthreads();

    const int lrow = tid >> 2;          // 0..63
    const int lk   = (tid & 3) * 4;     // 0,4,8,12
    const int p    = sp[lrow];
    const bool rowvalid = (p >= 0);
    const float* xrow  = x + (size_t)(rowvalid ? (p >> 1) : 0) * DD + lk;
    const float* wgrow = Wg + (size_t)e * FF * DD + (size_t)(n0 + lrow) * DD + lk;
    const float* wurow = Wu + (size_t)e * FF * DD + (size_t)(n0 + lrow) * DD + lk;

    const int tx = tid & 15, ty = tid >> 4;
    float ag[4][4] = {}, au[4][4] = {};

    for (int k0 = 0; k0 < DD; k0 += BK) {
        float4 av = *(const float4*)(xrow + k0);
        if (!rowvalid) av = make_float4(0.f, 0.f, 0.f, 0.f);
        float4 bg = *(const float4*)(wgrow + k0);
        float4 bu = *(const float4*)(wurow + k0);
        As[lk+0][lrow]=av.x; As[lk+1][lrow]=av.y; As[lk+2][lrow]=av.z; As[lk+3][lrow]=av.w;
        Bgs[lk+0][lrow]=bg.x; Bgs[lk+1][lrow]=bg.y; Bgs[lk+2][lrow]=bg.z; Bgs[lk+3][lrow]=bg.w;
        Bus[lk+0][lrow]=bu.x; Bus[lk+1][lrow]=bu.y; Bus[lk+2][lrow]=bu.z; Bus[lk+3][lrow]=bu.w;
        __syncthreads();
#pragma unroll
        for (int k = 0; k < BK; k++) {
            float4 a = *(const float4*)&As[k][ty * 4];
            float4 g = *(const float4*)&Bgs[k][tx * 4];
            float4 u = *(const float4*)&Bus[k][tx * 4];
            float aa[4] = {a.x, a.y, a.z, a.w};
            float gg[4] = {g.x, g.y, g.z, g.w};
            float uu[4] = {u.x, u.y, u.z, u.w};
#pragma unroll
            for (int i = 0; i < 4; i++)
#pragma unroll
                for (int j = 0; j < 4; j++) {
                    ag[i][j] = fmaf(aa[i], gg[j], ag[i][j]);
                    au[i][j] = fmaf(aa[i], uu[j], au[i][j]);
                }
        }
        __syncthreads();
    }

    // epilogue: h = silu(gate) * up  -> g_h[pair][n]
#pragma unroll
    for (int i = 0; i < 4; i++) {
        int pr = sp[ty * 4 + i];
        if (pr < 0) continue;
        float* hrow = g_h + (size_t)pr * FF + n0 + tx * 4;
        float4 hv;
        float* hvp = &hv.x;
#pragma unroll
        for (int j = 0; j < 4; j++) {
            float gv = ag[i][j];
            float sg = 1.f / (1.f + expf(-gv));
            hvp[j] = gv * sg * au[i][j];
        }
        *(float4*)hrow = hv;
    }
}

// ---------------------------------------------------------------------------
// Kernel: gathered down GEMM, scaled by routing weight, atomicAdd to out.
__global__ __launch_bounds__(256, 2) void ffn2_kernel(
    const float* __restrict__ Wd, float* __restrict__ out) {
    const int e   = blockIdx.z;
    const int cnt = g_count[e];
    const int m0  = blockIdx.y * BM;
    if (m0 >= cnt) return;
    const int n0  = blockIdx.x * BN;   // over D

    __shared__ float As[BK][BM];
    __shared__ float Bs[BK][BN];
    __shared__ int   sp[BM];
    __shared__ float sw[BM];

    const int tid = threadIdx.x;
    if (tid < BM) {
        int s = m0 + tid;
        sp[tid] = (s < cnt) ? g_pairs[e][s] : -1;
        sw[tid] = (s < cnt) ? g_wts[e][s] : 0.f;
    }
    __syncthreads();

    const int lrow = tid >> 2;
    const int lk   = (tid & 3) * 4;
    const int p    = sp[lrow];
    const bool rowvalid = (p >= 0);
    const float* hrow  = g_h + (size_t)(rowvalid ? p : 0) * FF + lk;
    const float* wdrow = Wd + (size_t)e * DD * FF + (size_t)(n0 + lrow) * FF + lk;

    const int tx = tid & 15, ty = tid >> 4;
    float acc[4][4] = {};

    for (int k0 = 0; k0 < FF; k0 += BK) {
        float4 av = *(const float4*)(hrow + k0);
        if (!rowvalid) av = make_float4(0.f, 0.f, 0.f, 0.f);
        float4 bv = *(const float4*)(wdrow + k0);
        As[lk+0][lrow]=av.x; As[lk+1][lrow]=av.y; As[lk+2][lrow]=av.z; As[lk+3][lrow]=av.w;
        Bs[lk+0][lrow]=bv.x; Bs[lk+1][lrow]=bv.y; Bs[lk+2][lrow]=bv.z; Bs[lk+3][lrow]=bv.w;
        __syncthreads();
#pragma unroll
        for (int k = 0; k < BK; k++) {
            float4 a = *(const float4*)&As[k][ty * 4];
            float4 b = *(const float4*)&Bs[k][tx * 4];
            float aa[4] = {a.x, a.y, a.z, a.w};
            float bb[4] = {b.x, b.y, b.z, b.w};
#pragma unroll
            for (int i = 0; i < 4; i++)
#pragma unroll
                for (int j = 0; j < 4; j++)
                    acc[i][j] = fmaf(aa[i], bb[j], acc[i][j]);
        }
        __syncthreads();
    }

#pragma unroll
    for (int i = 0; i < 4; i++) {
        int pr = sp[ty * 4 + i];
        if (pr < 0) continue;
        float w = sw[ty * 4 + i];
        int t = pr >> 1;
        float* orow = out + (size_t)t * DD + n0 + tx * 4;
#pragma unroll
        for (int j = 0; j < 4; j++)
            atomicAdd(&orow[j], acc[i][j] * w);
    }
}

// ---------------------------------------------------------------------------
extern "C" void kernel_launch(void* const* d_in, const int* in_sizes, int n_in,
                              void* d_out, int out_size) {
    const float* x     = (const float*)d_in[0];
    const float* Wgate = (const float*)d_in[1];
    const float* Wg    = (const float*)d_in[2];
    const float* Wu    = (const float*)d_in[3];
    const float* Wd    = (const float*)d_in[4];
    float* out = (float*)d_out;

    cudaMemsetAsync(d_out, 0, (size_t)out_size * sizeof(float), 0);
    zero_counts_kernel<<<1, 32>>>();
    router_kernel<<<NT / 8, 256>>>(x, Wgate);

    dim3 g1(FF / BN, NT / BM, NE);
    ffn1_kernel<<<g1, 256>>>(x, Wg, Wu);

    dim3 g2(DD / BN, NT / BM, NE);
    ffn2_kernel<<<g2, 256>>>(Wd, out);
}

// round 5
// speedup vs baseline: 3.9563x; 3.9563x over previous
#include <cuda_runtime.h>
#include <math.h>
#include <stdint.h>

// MoE FFN: T=8192 tokens, D=1024, F=4096, E=8, top-2.
// Inputs: x[T,D] f32, W_gate[E,D] f32, Wg[E,F,D] f32, Wu[E,F,D] f32, Wd[E,D,F] f32.
// Output: [T,D] f32.
// Tensor path: mma.sync m16n8k8 tf32 (base-ISA; tcgen05 rejected by sm_103 ptxas target).

#define NT 8192
#define DD 1024
#define FF 4096
#define NE 8

#define BM 128
#define BN 128
#define BK 32
#define KSTRIDE 36          // smem row stride in floats (pad 32 -> 36)

// ---------------- scratch ----------------
__device__ int   g_count[NE];
__device__ int   g_pairs[NE][NT];   // pair = token*2 + k
__device__ float g_wts[NE][NT];
__device__ float g_h[(size_t)NT * 2 * FF];   // 256 MiB

// ---------------- helpers ----------------
__device__ __forceinline__ uint32_t smem_u32(const void* p) {
    uint32_t a;
    asm("{ .reg .u64 t; cvta.to.shared.u64 t, %1; cvt.u32.u64 %0, t; }" : "=r"(a) : "l"(p));
    return a;
}
__device__ __forceinline__ uint32_t ldcvt(const float* p) {
    uint32_t r; asm("cvt.rna.tf32.f32 %0, %1;" : "=r"(r) : "f"(*p)); return r;
}
#define CPA16(dst, src, sz) \
    asm volatile("cp.async.cg.shared.global [%0], [%1], 16, %2;" \
                 :: "r"(dst), "l"(src), "r"(sz) : "memory")
#define CP_COMMIT() asm volatile("cp.async.commit_group;" ::: "memory")
#define CP_WAIT1()  asm volatile("cp.async.wait_group 1;" ::: "memory")

#define MMA_TF32(d, a, b) \
    asm volatile("mma.sync.aligned.m16n8k8.row.col.f32.tf32.tf32.f32 " \
        "{%0,%1,%2,%3}, {%4,%5,%6,%7}, {%8,%9}, {%0,%1,%2,%3};" \
        : "+f"((d)[0]), "+f"((d)[1]), "+f"((d)[2]), "+f"((d)[3]) \
        : "r"((a)[0]), "r"((a)[1]), "r"((a)[2]), "r"((a)[3]), \
          "r"((b)[0]), "r"((b)[1]))

// ---------------- router ----------------
__global__ void zero_counts_kernel() {
    if (threadIdx.x < NE) g_count[threadIdx.x] = 0;
}

__global__ void router_kernel(const float* __restrict__ x,
                              const float* __restrict__ Wgate) {
    int warp = (blockIdx.x * blockDim.x + threadIdx.x) >> 5;
    int lane = threadIdx.x & 31;
    if (warp >= NT) return;
    const float* xr = x + (size_t)warp * DD;

    float lg[NE];
#pragma unroll
    for (int e = 0; e < NE; e++) {
        const float* w = Wgate + e * DD;
        float acc = 0.f;
#pragma unroll 8
        for (int i = lane; i < DD; i += 32) acc = fmaf(xr[i], w[i], acc);
#pragma unroll
        for (int o = 16; o; o >>= 1) acc += __shfl_xor_sync(0xffffffffu, acc, o);
        lg[e] = acc;
    }
    if (lane == 0) {
        int e0 = 0;
#pragma unroll
        for (int e = 1; e < NE; e++) if (lg[e] > lg[e0]) e0 = e;
        int e1 = (e0 == 0) ? 1 : 0;
#pragma unroll
        for (int e = 0; e < NE; e++) {
            if (e == e0 || e == e1) continue;
            if (lg[e] > lg[e1]) e1 = e;
        }
        float w0 = 1.f / (1.f + expf(lg[e1] - lg[e0]));
        float w1 = 1.f - w0;
        int p0 = atomicAdd(&g_count[e0], 1);
        g_pairs[e0][p0] = warp * 2;     g_wts[e0][p0] = w0;
        int p1 = atomicAdd(&g_count[e1], 1);
        g_pairs[e1][p1] = warp * 2 + 1; g_wts[e1][p1] = w1;
    }
}

// ---------------- GEMM1: gate+up fused, mma.sync tf32 ----------------
// dyn smem floats: stage s at s*13824: A[128][36] @0, Bg @4608, Bu @9216
// sp[] at float offset 27648.  Total bytes = 110592 + 512 = 111104.
#define ST1 13824
#define SMEM1_BYTES (110592 + 512)

__global__ void __launch_bounds__(256, 1) ffn1_mma(const float* __restrict__ x,
                                                   const float* __restrict__ Wg,
                                                   const float* __restrict__ Wu) {
    const int e   = blockIdx.z;
    const int cnt = g_count[e];
    const int m0  = blockIdx.x * BM;
    if (m0 >= cnt) return;
    const int n0  = blockIdx.y * BN;

    extern __shared__ float S[];
    int* sp = (int*)(S + 27648);
    const uint32_t sb = smem_u32(S);
    const int tid = threadIdx.x;

    if (tid < BM) {
        int s = m0 + tid;
        sp[tid] = (s < cnt) ? g_pairs[e][s] : -1;
    }
    __syncthreads();

    // cp.async coords: row r0 + 32i, cols [c4, c4+4)
    const int r0 = tid >> 3;
    const int c4 = (tid & 7) * 4;
    const float* ap[4];
    uint32_t asz[4];
#pragma unroll
    for (int i = 0; i < 4; i++) {
        int p = sp[r0 + 32 * i];
        asz[i] = (p >= 0) ? 16u : 0u;
        ap[i] = x + (size_t)((p >= 0) ? (p >> 1) : 0) * DD + c4;
    }
    const float* wgb = Wg + (size_t)e * FF * DD + (size_t)(n0 + r0) * DD + c4;
    const float* wub = Wu + (size_t)e * FF * DD + (size_t)(n0 + r0) * DD + c4;
    const uint32_t rowb = (uint32_t)(r0 * KSTRIDE + c4) * 4u;  // byte off in tile

    const int lane = tid & 31;
    const int g  = lane >> 2;
    const int tg = lane & 3;
    const int wm = (tid >> 5) & 3;     // warp m: 0..3
    const int wn = tid >> 7;           // warp n: 0..1

    float accg[2][8][4], accu[2][8][4];
#pragma unroll
    for (int i = 0; i < 2; i++)
#pragma unroll
        for (int j = 0; j < 8; j++)
#pragma unroll
            for (int q = 0; q < 4; q++) { accg[i][j][q] = 0.f; accu[i][j][q] = 0.f; }

    const int NC = DD / BK;   // 32

    // prologue: chunk 0 -> stage 0
    {
        uint32_t sA = sb + rowb, sG = sb + 4608u * 4u + rowb, sU = sb + 9216u * 4u + rowb;
#pragma unroll
        for (int i = 0; i < 4; i++) {
            CPA16(sA + i * (32u * KSTRIDE * 4u), ap[i], asz[i]);
            CPA16(sG + i * (32u * KSTRIDE * 4u), wgb + (size_t)i * 32 * DD, 16u);
            CPA16(sU + i * (32u * KSTRIDE * 4u), wub + (size_t)i * 32 * DD, 16u);
        }
        CP_COMMIT();
    }

    for (int c = 0; c < NC; c++) {
        if (c + 1 < NC) {
            const int k0 = (c + 1) * BK;
            const uint32_t so = ((c + 1) & 1) ? (uint32_t)ST1 * 4u : 0u;
            uint32_t sA = sb + so + rowb, sG = sb + so + 4608u * 4u + rowb,
                     sU = sb + so + 9216u * 4u + rowb;
#pragma unroll
            for (int i = 0; i < 4; i++) {
                CPA16(sA + i * (32u * KSTRIDE * 4u), ap[i] + k0, asz[i]);
                CPA16(sG + i * (32u * KSTRIDE * 4u), wgb + (size_t)i * 32 * DD + k0, 16u);
                CPA16(sU + i * (32u * KSTRIDE * 4u), wub + (size_t)i * 32 * DD + k0, 16u);
            }
        }
        CP_COMMIT();
        CP_WAIT1();
        __syncthreads();

        const float* As = S + (c & 1) * ST1;
        const float* Bg = As + 4608;
        const float* Bu = As + 9216;

#pragma unroll
        for (int s = 0; s < 4; s++) {
            const int k = s * 8 + tg;
            uint32_t af[2][4];
#pragma unroll
            for (int i = 0; i < 2; i++) {
                const int rm = wm * 32 + i * 16 + g;
                af[i][0] = ldcvt(&As[rm * KSTRIDE + k]);
                af[i][1] = ldcvt(&As[(rm + 8) * KSTRIDE + k]);
                af[i][2] = ldcvt(&As[rm * KSTRIDE + k + 4]);
                af[i][3] = ldcvt(&As[(rm + 8) * KSTRIDE + k + 4]);
            }
#pragma unroll
            for (int j = 0; j < 8; j++) {
                const int rn = wn * 64 + j * 8 + g;
                uint32_t bg[2], bu[2];
                bg[0] = ldcvt(&Bg[rn * KSTRIDE + k]);
                bg[1] = ldcvt(&Bg[rn * KSTRIDE + k + 4]);
                bu[0] = ldcvt(&Bu[rn * KSTRIDE + k]);
                bu[1] = ldcvt(&Bu[rn * KSTRIDE + k + 4]);
                MMA_TF32(accg[0][j], af[0], bg);
                MMA_TF32(accg[1][j], af[1], bg);
                MMA_TF32(accu[0][j], af[0], bu);
                MMA_TF32(accu[1][j], af[1], bu);
            }
        }
        __syncthreads();
    }

    // epilogue: h = silu(gate)*up -> g_h[pair][col]
#pragma unroll
    for (int i = 0; i < 2; i++) {
#pragma unroll
        for (int half = 0; half < 2; half++) {
            const int rl = wm * 32 + i * 16 + g + half * 8;
            const int pr = sp[rl];
            if (pr < 0) continue;
            float* hrow = g_h + (size_t)pr * FF + n0 + wn * 64 + 2 * tg;
#pragma unroll
            for (int j = 0; j < 8; j++) {
                float gv0 = accg[i][j][half * 2 + 0];
                float gv1 = accg[i][j][half * 2 + 1];
                float2 hv;
                hv.x = gv0 / (1.f + expf(-gv0)) * accu[i][j][half * 2 + 0];
                hv.y = gv1 / (1.f + expf(-gv1)) * accu[i][j][half * 2 + 1];
                *(float2*)(hrow + j * 8) = hv;
            }
        }
    }
}

// ---------------- GEMM2: down proj, mma.sync tf32 ----------------
// dyn smem floats: stage s at s*9216: A[128][36] @0, B @4608
// sp at float 18432, sw at 18560. Total bytes = 73728 + 1024.
#define ST2 9216
#define SMEM2_BYTES (73728 + 1024)

__global__ void __launch_bounds__(256, 1) ffn2_mma(const float* __restrict__ Wd,
                                                   float* __restrict__ out) {
    const int e   = blockIdx.z;
    const int cnt = g_count[e];
    const int m0  = blockIdx.x * BM;
    if (m0 >= cnt) return;
    const int n0  = blockIdx.y * BN;   // over D

    extern __shared__ float S[];
    int*   sp = (int*)(S + 18432);
    float* sw = S + 18560;
    const uint32_t sb = smem_u32(S);
    const int tid = threadIdx.x;

    if (tid < BM) {
        int s = m0 + tid;
        sp[tid] = (s < cnt) ? g_pairs[e][s] : -1;
        sw[tid] = (s < cnt) ? g_wts[e][s] : 0.f;
    }
    __syncthreads();

    const int r0 = tid >> 3;
    const int c4 = (tid & 7) * 4;
    const float* ap[4];
    uint32_t asz[4];
#pragma unroll
    for (int i = 0; i < 4; i++) {
        int p = sp[r0 + 32 * i];
        asz[i] = (p >= 0) ? 16u : 0u;
        ap[i] = g_h + (size_t)((p >= 0) ? p : 0) * FF + c4;
    }
    const float* wb = Wd + (size_t)e * DD * FF + (size_t)(n0 + r0) * FF + c4;
    const uint32_t rowb = (uint32_t)(r0 * KSTRIDE + c4) * 4u;

    const int lane = tid & 31;
    const int g  = lane >> 2;
    const int tg = lane & 3;
    const int wm = (tid >> 5) & 3;
    const int wn = tid >> 7;

    float acc[2][8][4];
#pragma unroll
    for (int i = 0; i < 2; i++)
#pragma unroll
        for (int j = 0; j < 8; j++)
#pragma unroll
            for (int q = 0; q < 4; q++) acc[i][j][q] = 0.f;

    const int NC = FF / BK;   // 128

    {
        uint32_t sA = sb + rowb, sB = sb + 4608u * 4u + rowb;
#pragma unroll
        for (int i = 0; i < 4; i++) {
            CPA16(sA + i * (32u * KSTRIDE * 4u), ap[i], asz[i]);
            CPA16(sB + i * (32u * KSTRIDE * 4u), wb + (size_t)i * 32 * FF, 16u);
        }
        CP_COMMIT();
    }

    for (int c = 0; c < NC; c++) {
        if (c + 1 < NC) {
            const int k0 = (c + 1) * BK;
            const uint32_t so = ((c + 1) & 1) ? (uint32_t)ST2 * 4u : 0u;
            uint32_t sA = sb + so + rowb, sB = sb + so + 4608u * 4u + rowb;
#pragma unroll
            for (int i = 0; i < 4; i++) {
                CPA16(sA + i * (32u * KSTRIDE * 4u), ap[i] + k0, asz[i]);
                CPA16(sB + i * (32u * KSTRIDE * 4u), wb + (size_t)i * 32 * FF + k0, 16u);
            }
        }
        CP_COMMIT();
        CP_WAIT1();
        __syncthreads();

        const float* As = S + (c & 1) * ST2;
        const float* Bs = As + 4608;

#pragma unroll
        for (int s = 0; s < 4; s++) {
            const int k = s * 8 + tg;
            uint32_t af[2][4];
#pragma unroll
            for (int i = 0; i < 2; i++) {
                const int rm = wm * 32 + i * 16 + g;
                af[i][0] = ldcvt(&As[rm * KSTRIDE + k]);
                af[i][1] = ldcvt(&As[(rm + 8) * KSTRIDE + k]);
                af[i][2] = ldcvt(&As[rm * KSTRIDE + k + 4]);
                af[i][3] = ldcvt(&As[(rm + 8) * KSTRIDE + k + 4]);
            }
#pragma unroll
            for (int j = 0; j < 8; j++) {
                const int rn = wn * 64 + j * 8 + g;
                uint32_t bf[2];
                bf[0] = ldcvt(&Bs[rn * KSTRIDE + k]);
                bf[1] = ldcvt(&Bs[rn * KSTRIDE + k + 4]);
                MMA_TF32(acc[0][j], af[0], bf);
                MMA_TF32(acc[1][j], af[1], bf);
            }
        }
        __syncthreads();
    }

    // epilogue: out[token] += acc * w  (atomic across experts)
#pragma unroll
    for (int i = 0; i < 2; i++) {
#pragma unroll
        for (int half = 0; half < 2; half++) {
            const int rl = wm * 32 + i * 16 + g + half * 8;
            const int pr = sp[rl];
            if (pr < 0) continue;
            const float w = sw[rl];
            const int tok = pr >> 1;
            float* orow = out + (size_t)tok * DD + n0 + wn * 64 + 2 * tg;
#pragma unroll
            for (int j = 0; j < 8; j++) {
                atomicAdd(&orow[j * 8 + 0], acc[i][j][half * 2 + 0] * w);
                atomicAdd(&orow[j * 8 + 1], acc[i][j][half * 2 + 1] * w);
            }
        }
    }
}

// ---------------------------------------------------------------------------
extern "C" void kernel_launch(void* const* d_in, const int* in_sizes, int n_in,
                              void* d_out, int out_size) {
    const float* x     = (const float*)d_in[0];
    const float* Wgate = (const float*)d_in[1];
    const float* Wg    = (const float*)d_in[2];
    const float* Wu    = (const float*)d_in[3];
    const float* Wd    = (const float*)d_in[4];
    float* out = (float*)d_out;

    cudaFuncSetAttribute(ffn1_mma, cudaFuncAttributeMaxDynamicSharedMemorySize, SMEM1_BYTES);
    cudaFuncSetAttribute(ffn2_mma, cudaFuncAttributeMaxDynamicSharedMemorySize, SMEM2_BYTES);

    cudaMemsetAsync(d_out, 0, (size_t)out_size * sizeof(float), 0);
    zero_counts_kernel<<<1, 32>>>();
    router_kernel<<<NT / 8, 256>>>(x, Wgate);

    dim3 g1(NT / BM, FF / BN, NE);
    ffn1_mma<<<g1, 256, SMEM1_BYTES>>>(x, Wg, Wu);

    dim3 g2(NT / BM, DD / BN, NE);
    ffn2_mma<<<g2, 256, SMEM2_BYTES>>>(Wd, out);
}

// round 7
// speedup vs baseline: 3.9678x; 1.0029x over previous
#include <cuda_runtime.h>
#include <math.h>
#include <stdint.h>

// MoE FFN: T=8192 tokens, D=1024, F=4096, E=8, top-2.
// Inputs: x[T,D] f32, W_gate[E,D] f32, Wg[E,F,D] f32, Wu[E,F,D] f32, Wd[E,D,F] f32.
// Output: [T,D] f32.
// Tensor path: mma.sync m16n8k8 tf32 (base-ISA; tcgen05 rejected on sm_103 target).
// R6: pre-rounded tf32 operand copies (no cvt in hot loop), 3-stage cp.async,
//     store+combine instead of atomics.

#define NT 8192
#define DD 1024
#define FF 4096
#define NE 8

#define BM 128
#define BN 128
#define BK 32
#define KSTRIDE 36          // smem row stride in floats (pad 32 -> 36)

// ---------------- scratch ----------------
__device__ int   g_count[NE];
__device__ int   g_pairs[NE][NT];   // pair = token*2 + k
__device__ float g_wts[NE][NT];
__device__ float g_h[(size_t)NT * 2 * FF];     // 256 MiB (tf32-rounded)
__device__ float g_o[(size_t)NT * 2 * DD];     // 64 MiB per-pair outputs
__device__ float g_xc[(size_t)NT * DD];        // tf32-rounded x
__device__ float g_wgc[(size_t)NE * FF * DD];  // tf32-rounded Wg (134MB)
__device__ float g_wuc[(size_t)NE * FF * DD];
__device__ float g_wdc[(size_t)NE * DD * FF];

// ---------------- helpers ----------------
__device__ __forceinline__ uint32_t smem_u32(const void* p) {
    uint32_t a;
    asm("{ .reg .u64 t; cvta.to.shared.u64 t, %1; cvt.u32.u64 %0, t; }" : "=r"(a) : "l"(p));
    return a;
}
__device__ __forceinline__ float tf32r(float x) {
    uint32_t r; asm("cvt.rna.tf32.f32 %0, %1;" : "=r"(r) : "f"(x));
    return __uint_as_float(r);
}
#define CPA16(dst, src, sz) \
    asm volatile("cp.async.cg.shared.global [%0], [%1], 16, %2;" \
                 :: "r"(dst), "l"(src), "r"(sz) : "memory")
#define CP_COMMIT() asm volatile("cp.async.commit_group;" ::: "memory")
#define CP_WAIT2()  asm volatile("cp.async.wait_group 2;" ::: "memory")

#define MMA_TF32(d, a, b) \
    asm volatile("mma.sync.aligned.m16n8k8.row.col.f32.tf32.tf32.f32 " \
        "{%0,%1,%2,%3}, {%4,%5,%6,%7}, {%8,%9}, {%0,%1,%2,%3};" \
        : "+f"((d)[0]), "+f"((d)[1]), "+f"((d)[2]), "+f"((d)[3]) \
        : "r"((a)[0]), "r"((a)[1]), "r"((a)[2]), "r"((a)[3]), \
          "r"((b)[0]), "r"((b)[1]))

// ---------------- tf32 pre-round pass ----------------
__global__ void cvt_kernel(const float4* __restrict__ src, float4* __restrict__ dst,
                           int n4) {
    int i = blockIdx.x * blockDim.x + threadIdx.x;
    if (i >= n4) return;
    float4 v = src[i];
    v.x = tf32r(v.x); v.y = tf32r(v.y); v.z = tf32r(v.z); v.w = tf32r(v.w);
    dst[i] = v;
}

// ---------------- router ----------------
__global__ void zero_counts_kernel() {
    if (threadIdx.x < NE) g_count[threadIdx.x] = 0;
}

__global__ void router_kernel(const float* __restrict__ x,
                              const float* __restrict__ Wgate) {
    int warp = (blockIdx.x * blockDim.x + threadIdx.x) >> 5;
    int lane = threadIdx.x & 31;
    if (warp >= NT) return;
    const float* xr = x + (size_t)warp * DD;

    float lg[NE];
#pragma unroll
    for (int e = 0; e < NE; e++) {
        const float* w = Wgate + e * DD;
        float acc = 0.f;
#pragma unroll 8
        for (int i = lane; i < DD; i += 32) acc = fmaf(xr[i], w[i], acc);
#pragma unroll
        for (int o = 16; o; o >>= 1) acc += __shfl_xor_sync(0xffffffffu, acc, o);
        lg[e] = acc;
    }
    if (lane == 0) {
        int e0 = 0;
#pragma unroll
        for (int e = 1; e < NE; e++) if (lg[e] > lg[e0]) e0 = e;
        int e1 = (e0 == 0) ? 1 : 0;
#pragma unroll
        for (int e = 0; e < NE; e++) {
            if (e == e0 || e == e1) continue;
            if (lg[e] > lg[e1]) e1 = e;
        }
        float w0 = 1.f / (1.f + expf(lg[e1] - lg[e0]));
        float w1 = 1.f - w0;
        int p0 = atomicAdd(&g_count[e0], 1);
        g_pairs[e0][p0] = warp * 2;     g_wts[e0][p0] = w0;
        int p1 = atomicAdd(&g_count[e1], 1);
        g_pairs[e1][p1] = warp * 2 + 1; g_wts[e1][p1] = w1;
    }
}

// ---------------- GEMM1: gate+up fused ----------------
// dyn smem floats: stage s (s=0..2) at s*13824: A[128][36] @0, Bg @4608, Bu @9216
// sp[] at float offset 41472.  Bytes = 165888 + 512.
#define ST1 13824
#define SMEM1_BYTES (165888 + 512)

__global__ void __launch_bounds__(256, 1) ffn1_mma(const float* __restrict__ Wg_unused,
                                                   const float* __restrict__ Wu_unused) {
    const int e   = blockIdx.z;
    const int cnt = g_count[e];
    const int m0  = blockIdx.x * BM;
    if (m0 >= cnt) return;
    const int n0  = blockIdx.y * BN;

    extern __shared__ float S[];
    int* sp = (int*)(S + 41472);
    const uint32_t sb = smem_u32(S);
    const int tid = threadIdx.x;

    if (tid < BM) {
        int s = m0 + tid;
        sp[tid] = (s < cnt) ? g_pairs[e][s] : -1;
    }
    __syncthreads();

    // cp.async coords: row r0 + 32i, cols [c4, c4+4)
    const int r0 = tid >> 3;
    const int c4 = (tid & 7) * 4;
    const float* ap[4];
    uint32_t asz[4];
#pragma unroll
    for (int i = 0; i < 4; i++) {
        int p = sp[r0 + 32 * i];
        asz[i] = (p >= 0) ? 16u : 0u;
        ap[i] = g_xc + (size_t)((p >= 0) ? (p >> 1) : 0) * DD + c4;
    }
    const float* wgb = g_wgc + (size_t)e * FF * DD + (size_t)(n0 + r0) * DD + c4;
    const float* wub = g_wuc + (size_t)e * FF * DD + (size_t)(n0 + r0) * DD + c4;
    const uint32_t rowb = (uint32_t)(r0 * KSTRIDE + c4) * 4u;

    const int lane = tid & 31;
    const int g  = lane >> 2;
    const int tg = lane & 3;
    const int wm = (tid >> 5) & 3;
    const int wn = tid >> 7;

    float accg[2][8][4], accu[2][8][4];
#pragma unroll
    for (int i = 0; i < 2; i++)
#pragma unroll
        for (int j = 0; j < 8; j++)
#pragma unroll
            for (int q = 0; q < 4; q++) { accg[i][j][q] = 0.f; accu[i][j][q] = 0.f; }

    const int NC = DD / BK;   // 32

    auto fill = [&](int ch) {
        const uint32_t so = (uint32_t)(ch % 3) * ((uint32_t)ST1 * 4u);
        const int k0 = ch * BK;
        uint32_t sA = sb + so + rowb;
        uint32_t sG = sA + 4608u * 4u;
        uint32_t sU = sA + 9216u * 4u;
#pragma unroll
        for (int i = 0; i < 4; i++) {
            CPA16(sA + i * (32u * KSTRIDE * 4u), ap[i] + k0, asz[i]);
            CPA16(sG + i * (32u * KSTRIDE * 4u), wgb + (size_t)i * 32 * DD + k0, 16u);
            CPA16(sU + i * (32u * KSTRIDE * 4u), wub + (size_t)i * 32 * DD + k0, 16u);
        }
    };

    fill(0); CP_COMMIT();
    fill(1); CP_COMMIT();

    for (int c = 0; c < NC; c++) {
        if (c + 2 < NC) fill(c + 2);
        CP_COMMIT();
        CP_WAIT2();
        __syncthreads();

        const uint32_t* As = (const uint32_t*)(S + (c % 3) * ST1);
        const uint32_t* Bg = As + 4608;
        const uint32_t* Bu = As + 9216;

#pragma unroll
        for (int s = 0; s < 4; s++) {
            const int k = s * 8 + tg;
            uint32_t af[2][4];
#pragma unroll
            for (int i = 0; i < 2; i++) {
                const int rm = wm * 32 + i * 16 + g;
                af[i][0] = As[rm * KSTRIDE + k];
                af[i][1] = As[(rm + 8) * KSTRIDE + k];
                af[i][2] = As[rm * KSTRIDE + k + 4];
                af[i][3] = As[(rm + 8) * KSTRIDE + k + 4];
            }
#pragma unroll
            for (int j = 0; j < 8; j++) {
                const int rn = wn * 64 + j * 8 + g;
                uint32_t bg[2], bu[2];
                bg[0] = Bg[rn * KSTRIDE + k];
                bg[1] = Bg[rn * KSTRIDE + k + 4];
                bu[0] = Bu[rn * KSTRIDE + k];
                bu[1] = Bu[rn * KSTRIDE + k + 4];
                MMA_TF32(accg[0][j], af[0], bg);
                MMA_TF32(accg[1][j], af[1], bg);
                MMA_TF32(accu[0][j], af[0], bu);
                MMA_TF32(accu[1][j], af[1], bu);
            }
        }
        __syncthreads();
    }

    // epilogue: h = tf32_round(silu(gate)*up) -> g_h[pair][col]
#pragma unroll
    for (int i = 0; i < 2; i++) {
#pragma unroll
        for (int half = 0; half < 2; half++) {
            const int rl = wm * 32 + i * 16 + g + half * 8;
            const int pr = sp[rl];
            if (pr < 0) continue;
            float* hrow = g_h + (size_t)pr * FF + n0 + wn * 64 + 2 * tg;
#pragma unroll
            for (int j = 0; j < 8; j++) {
                float gv0 = accg[i][j][half * 2 + 0];
                float gv1 = accg[i][j][half * 2 + 1];
                float2 hv;
                hv.x = tf32r(gv0 / (1.f + expf(-gv0)) * accu[i][j][half * 2 + 0]);
                hv.y = tf32r(gv1 / (1.f + expf(-gv1)) * accu[i][j][half * 2 + 1]);
                *(float2*)(hrow + j * 8) = hv;
            }
        }
    }
}

// ---------------- GEMM2: down proj ----------------
// dyn smem floats: stage s (0..2) at s*9216: A[128][36] @0, B @4608
// sp at float 27648, sw at 27776. Bytes = 110592 + 1024.
#define ST2 9216
#define SMEM2_BYTES (110592 + 1024)

__global__ void __launch_bounds__(256, 2) ffn2_mma() {
    const int e   = blockIdx.z;
    const int cnt = g_count[e];
    const int m0  = blockIdx.x * BM;
    if (m0 >= cnt) return;
    const int n0  = blockIdx.y * BN;   // over D

    extern __shared__ float S[];
    int*   sp = (int*)(S + 27648);
    float* sw = S + 27776;
    const uint32_t sb = smem_u32(S);
    const int tid = threadIdx.x;

    if (tid < BM) {
        int s = m0 + tid;
        sp[tid] = (s < cnt) ? g_pairs[e][s] : -1;
        sw[tid] = (s < cnt) ? g_wts[e][s] : 0.f;
    }
    __syncthreads();

    const int r0 = tid >> 3;
    const int c4 = (tid & 7) * 4;
    const float* ap[4];
    uint32_t asz[4];
#pragma unroll
    for (int i = 0; i < 4; i++) {
        int p = sp[r0 + 32 * i];
        asz[i] = (p >= 0) ? 16u : 0u;
        ap[i] = g_h + (size_t)((p >= 0) ? p : 0) * FF + c4;
    }
    const float* wb = g_wdc + (size_t)e * DD * FF + (size_t)(n0 + r0) * FF + c4;
    const uint32_t rowb = (uint32_t)(r0 * KSTRIDE + c4) * 4u;

    const int lane = tid & 31;
    const int g  = lane >> 2;
    const int tg = lane & 3;
    const int wm = (tid >> 5) & 3;
    const int wn = tid >> 7;

    float acc[2][8][4];
#pragma unroll
    for (int i = 0; i < 2; i++)
#pragma unroll
        for (int j = 0; j < 8; j++)
#pragma unroll
            for (int q = 0; q < 4; q++) acc[i][j][q] = 0.f;

    const int NC = FF / BK;   // 128

    auto fill = [&](int ch) {
        const uint32_t so = (uint32_t)(ch % 3) * ((uint32_t)ST2 * 4u);
        const int k0 = ch * BK;
        uint32_t sA = sb + so + rowb;
        uint32_t sB = sA + 4608u * 4u;
#pragma unroll
        for (int i = 0; i < 4; i++) {
            CPA16(sA + i * (32u * KSTRIDE * 4u), ap[i] + k0, asz[i]);
            CPA16(sB + i * (32u * KSTRIDE * 4u), wb + (size_t)i * 32 * FF + k0, 16u);
        }
    };

    fill(0); CP_COMMIT();
    fill(1); CP_COMMIT();

    for (int c = 0; c < NC; c++) {
        if (c + 2 < NC) fill(c + 2);
        CP_COMMIT();
        CP_WAIT2();
        __syncthreads();

        const uint32_t* As = (const uint32_t*)(S + (c % 3) * ST2);
        const uint32_t* Bs = As + 4608;

#pragma unroll
        for (int s = 0; s < 4; s++) {
            const int k = s * 8 + tg;
            uint32_t af[2][4];
#pragma unroll
            for (int i = 0; i < 2; i++) {
                const int rm = wm * 32 + i * 16 + g;
                af[i][0] = As[rm * KSTRIDE + k];
                af[i][1] = As[(rm + 8) * KSTRIDE + k];
                af[i][2] = As[rm * KSTRIDE + k + 4];
                af[i][3] = As[(rm + 8) * KSTRIDE + k + 4];
            }
#pragma unroll
            for (int j = 0; j < 8; j++) {
                const int rn = wn * 64 + j * 8 + g;
                uint32_t bf[2];
                bf[0] = Bs[rn * KSTRIDE + k];
                bf[1] = Bs[rn * KSTRIDE + k + 4];
                MMA_TF32(acc[0][j], af[0], bf);
                MMA_TF32(acc[1][j], af[1], bf);
            }
        }
        __syncthreads();
    }

    // epilogue: g_o[pair] = acc * w  (plain stores; combine kernel sums)
#pragma unroll
    for (int i = 0; i < 2; i++) {
#pragma unroll
        for (int half = 0; half < 2; half++) {
            const int rl = wm * 32 + i * 16 + g + half * 8;
            const int pr = sp[rl];
            if (pr < 0) continue;
            const float w = sw[rl];
            float* orow = g_o + (size_t)pr * DD + n0 + wn * 64 + 2 * tg;
#pragma unroll
            for (int j = 0; j < 8; j++) {
                float2 ov;
                ov.x = acc[i][j][half * 2 + 0] * w;
                ov.y = acc[i][j][half * 2 + 1] * w;
                *(float2*)(orow + j * 8) = ov;
            }
        }
    }
}

// ---------------- combine: out[t] = g_o[2t] + g_o[2t+1] ----------------
__global__ void combine_kernel(float4* __restrict__ out) {
    int i = blockIdx.x * blockDim.x + threadIdx.x;   // over NT*DD/4
    if (i >= NT * DD / 4) return;
    const int t  = i / (DD / 4);
    const int d4 = i % (DD / 4);
    const float4* a = (const float4*)(g_o + (size_t)(2 * t) * DD) + d4;
    const float4* b = (const float4*)(g_o + (size_t)(2 * t + 1) * DD) + d4;
    float4 va = *a, vb = *b;
    va.x += vb.x; va.y += vb.y; va.z += vb.z; va.w += vb.w;
    out[i] = va;
}

// ---------------------------------------------------------------------------
extern "C" void kernel_launch(void* const* d_in, const int* in_sizes, int n_in,
                              void* d_out, int out_size) {
    const float* x     = (const float*)d_in[0];
    const float* Wgate = (const float*)d_in[1];
    const float* Wg    = (const float*)d_in[2];
    const float* Wu    = (const float*)d_in[3];
    const float* Wd    = (const float*)d_in[4];
    float* out = (float*)d_out;

    cudaFuncSetAttribute(ffn1_mma, cudaFuncAttributeMaxDynamicSharedMemorySize, SMEM1_BYTES);
    cudaFuncSetAttribute(ffn2_mma, cudaFuncAttributeMaxDynamicSharedMemorySize, SMEM2_BYTES);

    // tf32 pre-round copies
    float *g_xc_p, *g_wgc_p, *g_wuc_p, *g_wdc_p;
    cudaGetSymbolAddress((void**)&g_xc_p,  g_xc);
    cudaGetSymbolAddress((void**)&g_wgc_p, g_wgc);
    cudaGetSymbolAddress((void**)&g_wuc_p, g_wuc);
    cudaGetSymbolAddress((void**)&g_wdc_p, g_wdc);

    const int n4x = NT * DD / 4;               // 2,097,152
    const int n4w = NE * FF * DD / 4;          // 8,388,608
    cvt_kernel<<<(n4x + 255) / 256, 256>>>((const float4*)x,  (float4*)g_xc_p,  n4x);
    cvt_kernel<<<(n4w + 255) / 256, 256>>>((const float4*)Wg, (float4*)g_wgc_p, n4w);
    cvt_kernel<<<(n4w + 255) / 256, 256>>>((const float4*)Wu, (float4*)g_wuc_p, n4w);
    cvt_kernel<<<(n4w + 255) / 256, 256>>>((const float4*)Wd, (float4*)g_wdc_p, n4w);

    zero_counts_kernel<<<1, 32>>>();
    router_kernel<<<NT / 8, 256>>>(x, Wgate);

    dim3 g1(NT / BM, FF / BN, NE);
    ffn1_mma<<<g1, 256, SMEM1_BYTES>>>(Wg, Wu);

    dim3 g2(NT / BM, DD / BN, NE);
    ffn2_mma<<<g2, 256, SMEM2_BYTES>>>();

    combine_kernel<<<(NT * DD / 4 + 255) / 256, 256>>>((float4*)out);
}

// round 8
// speedup vs baseline: 4.1612x; 1.0488x over previous
#include <cuda_runtime.h>
#include <math.h>
#include <stdint.h>

// MoE FFN: T=8192 tokens, D=1024, F=4096, E=8, top-2.
// Inputs: x[T,D] f32, W_gate[E,D] f32, Wg[E,F,D] f32, Wu[E,F,D] f32, Wd[E,D,F] f32.
// Output: [T,D] f32.
// Tensor path: mma.sync m16n8k8 tf32 + ldmatrix fragment loads (base ISA).

#define NT 8192
#define DD 1024
#define FF 4096
#define NE 8

#define BM 128
#define BN 128
#define BK 32
#define KSTRIDE 36          // smem row stride in floats (pad 32 -> 36)

// ---------------- scratch ----------------
__device__ int   g_count[NE];
__device__ int   g_pairs[NE][NT];   // pair = token*2 + k
__device__ float g_wts[NE][NT];
__device__ float g_h[(size_t)NT * 2 * FF];     // 256 MiB (tf32-rounded)
__device__ float g_o[(size_t)NT * 2 * DD];     // 64 MiB per-pair outputs
__device__ float g_xc[(size_t)NT * DD];        // tf32-rounded x
__device__ float g_wgc[(size_t)NE * FF * DD];  // tf32-rounded Wg
__device__ float g_wuc[(size_t)NE * FF * DD];
__device__ float g_wdc[(size_t)NE * DD * FF];

// ---------------- helpers ----------------
__device__ __forceinline__ uint32_t smem_u32(const void* p) {
    uint32_t a;
    asm("{ .reg .u64 t; cvta.to.shared.u64 t, %1; cvt.u32.u64 %0, t; }" : "=r"(a) : "l"(p));
    return a;
}
__device__ __forceinline__ float tf32r(float x) {
    uint32_t r; asm("cvt.rna.tf32.f32 %0, %1;" : "=r"(r) : "f"(x));
    return __uint_as_float(r);
}
#define CPA16(dst, src, sz) \
    asm volatile("cp.async.cg.shared.global [%0], [%1], 16, %2;" \
                 :: "r"(dst), "l"(src), "r"(sz) : "memory")
#define CP_COMMIT() asm volatile("cp.async.commit_group;" ::: "memory")
#define CP_WAIT2()  asm volatile("cp.async.wait_group 2;" ::: "memory")

#define MMA_TF32(d, a0, a1, a2, a3, b0, b1) \
    asm volatile("mma.sync.aligned.m16n8k8.row.col.f32.tf32.tf32.f32 " \
        "{%0,%1,%2,%3}, {%4,%5,%6,%7}, {%8,%9}, {%0,%1,%2,%3};" \
        : "+f"((d)[0]), "+f"((d)[1]), "+f"((d)[2]), "+f"((d)[3]) \
        : "r"(a0), "r"(a1), "r"(a2), "r"(a3), "r"(b0), "r"(b1))

#define LDSM4(r0, r1, r2, r3, addr) \
    asm volatile("ldmatrix.sync.aligned.m8n8.x4.shared.b16 {%0,%1,%2,%3}, [%4];" \
        : "=r"(r0), "=r"(r1), "=r"(r2), "=r"(r3) : "r"(addr))

// ---------------- tf32 pre-round pass ----------------
__global__ void cvt_kernel(const float4* __restrict__ src, float4* __restrict__ dst,
                           int n4) {
    int i = blockIdx.x * blockDim.x + threadIdx.x;
    if (i >= n4) return;
    float4 v = src[i];
    v.x = tf32r(v.x); v.y = tf32r(v.y); v.z = tf32r(v.z); v.w = tf32r(v.w);
    dst[i] = v;
}

// ---------------- router ----------------
__global__ void zero_counts_kernel() {
    if (threadIdx.x < NE) g_count[threadIdx.x] = 0;
}

__global__ void router_kernel(const float* __restrict__ x,
                              const float* __restrict__ Wgate) {
    int warp = (blockIdx.x * blockDim.x + threadIdx.x) >> 5;
    int lane = threadIdx.x & 31;
    if (warp >= NT) return;
    const float* xr = x + (size_t)warp * DD;

    float lg[NE];
#pragma unroll
    for (int e = 0; e < NE; e++) {
        const float* w = Wgate + e * DD;
        float acc = 0.f;
#pragma unroll 8
        for (int i = lane; i < DD; i += 32) acc = fmaf(xr[i], w[i], acc);
#pragma unroll
        for (int o = 16; o; o >>= 1) acc += __shfl_xor_sync(0xffffffffu, acc, o);
        lg[e] = acc;
    }
    if (lane == 0) {
        int e0 = 0;
#pragma unroll
        for (int e = 1; e < NE; e++) if (lg[e] > lg[e0]) e0 = e;
        int e1 = (e0 == 0) ? 1 : 0;
#pragma unroll
        for (int e = 0; e < NE; e++) {
            if (e == e0 || e == e1) continue;
            if (lg[e] > lg[e1]) e1 = e;
        }
        float w0 = 1.f / (1.f + expf(lg[e1] - lg[e0]));
        float w1 = 1.f - w0;
        int p0 = atomicAdd(&g_count[e0], 1);
        g_pairs[e0][p0] = warp * 2;     g_wts[e0][p0] = w0;
        int p1 = atomicAdd(&g_count[e1], 1);
        g_pairs[e1][p1] = warp * 2 + 1; g_wts[e1][p1] = w1;
    }
}

// ---------------- GEMM1: gate+up fused ----------------
// dyn smem floats: stage s (0..2) at s*13824: A[128][36] @0, Bg @4608, Bu @9216
// sp[] at float offset 41472.  Bytes = 165888 + 512.
#define ST1 13824
#define SMEM1_BYTES (165888 + 512)

__global__ void __launch_bounds__(256, 1) ffn1_mma() {
    const int e   = blockIdx.z;
    const int cnt = g_count[e];
    const int m0  = blockIdx.x * BM;
    if (m0 >= cnt) return;
    const int n0  = blockIdx.y * BN;

    extern __shared__ float S[];
    int* sp = (int*)(S + 41472);
    const uint32_t sb = smem_u32(S);
    const int tid = threadIdx.x;

    if (tid < BM) {
        int s = m0 + tid;
        sp[tid] = (s < cnt) ? g_pairs[e][s] : -1;
    }
    __syncthreads();

    // cp.async coords: row r0 + 32i, cols [c4, c4+4)
    const int r0 = tid >> 3;
    const int c4 = (tid & 7) * 4;
    const float* ap[4];
    uint32_t asz[4];
#pragma unroll
    for (int i = 0; i < 4; i++) {
        int p = sp[r0 + 32 * i];
        asz[i] = (p >= 0) ? 16u : 0u;
        ap[i] = g_xc + (size_t)((p >= 0) ? (p >> 1) : 0) * DD + c4;
    }
    const float* wgb = g_wgc + (size_t)e * FF * DD + (size_t)(n0 + r0) * DD + c4;
    const float* wub = g_wuc + (size_t)e * FF * DD + (size_t)(n0 + r0) * DD + c4;
    const uint32_t rowb = (uint32_t)(r0 * KSTRIDE + c4) * 4u;

    const int lane = tid & 31;
    const int g  = lane >> 2;
    const int tg = lane & 3;
    const int wm = (tid >> 5) & 3;
    const int wn = tid >> 7;

    // ldmatrix per-lane byte offsets (within one stage)
    const int lt = lane >> 3;     // tile 0..3
    const int tr = lane & 7;      // row in tile
    // A frag i: tiles {rows rm_i+(lt&1)*8+tr, cols (lt>>1)*4}
    uint32_t aoff[2];
#pragma unroll
    for (int i = 0; i < 2; i++) {
        int row = wm * 32 + i * 16 + (lt & 1) * 8 + tr;
        aoff[i] = (uint32_t)(row * KSTRIDE + (lt >> 1) * 4) * 4u;
    }
    // B j-pair p: tiles {rows rn0+(lt>>1)*8+tr, cols (lt&1)*4}, rn0 = wn*64+p*16
    uint32_t boff[4];
#pragma unroll
    for (int p = 0; p < 4; p++) {
        int row = wn * 64 + p * 16 + (lt >> 1) * 8 + tr;
        boff[p] = (uint32_t)(row * KSTRIDE + (lt & 1) * 4) * 4u;
    }

    float accg[2][8][4], accu[2][8][4];
#pragma unroll
    for (int i = 0; i < 2; i++)
#pragma unroll
        for (int j = 0; j < 8; j++)
#pragma unroll
            for (int q = 0; q < 4; q++) { accg[i][j][q] = 0.f; accu[i][j][q] = 0.f; }

    const int NC = DD / BK;   // 32

    auto fill = [&](int ch) {
        const uint32_t so = (uint32_t)(ch % 3) * ((uint32_t)ST1 * 4u);
        const int k0 = ch * BK;
        uint32_t sA = sb + so + rowb;
        uint32_t sG = sA + 4608u * 4u;
        uint32_t sU = sA + 9216u * 4u;
#pragma unroll
        for (int i = 0; i < 4; i++) {
            CPA16(sA + i * (32u * KSTRIDE * 4u), ap[i] + k0, asz[i]);
            CPA16(sG + i * (32u * KSTRIDE * 4u), wgb + (size_t)i * 32 * DD + k0, 16u);
            CPA16(sU + i * (32u * KSTRIDE * 4u), wub + (size_t)i * 32 * DD + k0, 16u);
        }
    };

    fill(0); CP_COMMIT();
    fill(1); CP_COMMIT();

    for (int c = 0; c < NC; c++) {
        if (c + 2 < NC) fill(c + 2);
        CP_COMMIT();
        CP_WAIT2();
        __syncthreads();

        const uint32_t stg = sb + (uint32_t)(c % 3) * ((uint32_t)ST1 * 4u);
        const uint32_t sG  = stg + 4608u * 4u;
        const uint32_t sU  = stg + 9216u * 4u;

#pragma unroll
        for (int s = 0; s < 4; s++) {
            const uint32_t kb = (uint32_t)s * 32u;   // s*8 floats
            uint32_t af[2][4];
            LDSM4(af[0][0], af[0][1], af[0][2], af[0][3], stg + aoff[0] + kb);
            LDSM4(af[1][0], af[1][1], af[1][2], af[1][3], stg + aoff[1] + kb);
#pragma unroll
            for (int p = 0; p < 4; p++) {
                uint32_t bg0, bg1, bg2, bg3, bu0, bu1, bu2, bu3;
                LDSM4(bg0, bg1, bg2, bg3, sG + boff[p] + kb);
                LDSM4(bu0, bu1, bu2, bu3, sU + boff[p] + kb);
                const int j0 = p * 2, j1 = p * 2 + 1;
                MMA_TF32(accg[0][j0], af[0][0], af[0][1], af[0][2], af[0][3], bg0, bg1);
                MMA_TF32(accg[1][j0], af[1][0], af[1][1], af[1][2], af[1][3], bg0, bg1);
                MMA_TF32(accg[0][j1], af[0][0], af[0][1], af[0][2], af[0][3], bg2, bg3);
                MMA_TF32(accg[1][j1], af[1][0], af[1][1], af[1][2], af[1][3], bg2, bg3);
                MMA_TF32(accu[0][j0], af[0][0], af[0][1], af[0][2], af[0][3], bu0, bu1);
                MMA_TF32(accu[1][j0], af[1][0], af[1][1], af[1][2], af[1][3], bu0, bu1);
                MMA_TF32(accu[0][j1], af[0][0], af[0][1], af[0][2], af[0][3], bu2, bu3);
                MMA_TF32(accu[1][j1], af[1][0], af[1][1], af[1][2], af[1][3], bu2, bu3);
            }
        }
        __syncthreads();
    }

    // epilogue: h = tf32_round(silu(gate)*up) -> g_h[pair][col]
    // acc element q of j covers col n0 + wn*64 + j*8 + 2*tg + (q&1), row +8 if q>=2
#pragma unroll
    for (int i = 0; i < 2; i++) {
#pragma unroll
        for (int half = 0; half < 2; half++) {
            const int rl = wm * 32 + i * 16 + g + half * 8;
            const int pr = sp[rl];
            if (pr < 0) continue;
            float* hrow = g_h + (size_t)pr * FF + n0 + wn * 64 + 2 * tg;
#pragma unroll
            for (int j = 0; j < 8; j++) {
                float gv0 = accg[i][j][half * 2 + 0];
                float gv1 = accg[i][j][half * 2 + 1];
                float2 hv;
                hv.x = tf32r(gv0 / (1.f + expf(-gv0)) * accu[i][j][half * 2 + 0]);
                hv.y = tf32r(gv1 / (1.f + expf(-gv1)) * accu[i][j][half * 2 + 1]);
                *(float2*)(hrow + j * 8) = hv;
            }
        }
    }
}

// ---------------- GEMM2: down proj ----------------
// dyn smem floats: stage s (0..2) at s*9216: A[128][36] @0, B @4608
// sp at float 27648, sw at 27776. Bytes = 110592 + 1024.
#define ST2 9216
#define SMEM2_BYTES (110592 + 1024)

__global__ void __launch_bounds__(256, 2) ffn2_mma() {
    const int e   = blockIdx.z;
    const int cnt = g_count[e];
    const int m0  = blockIdx.x * BM;
    if (m0 >= cnt) return;
    const int n0  = blockIdx.y * BN;   // over D

    extern __shared__ float S[];
    int*   sp = (int*)(S + 27648);
    float* sw = S + 27776;
    const uint32_t sb = smem_u32(S);
    const int tid = threadIdx.x;

    if (tid < BM) {
        int s = m0 + tid;
        sp[tid] = (s < cnt) ? g_pairs[e][s] : -1;
        sw[tid] = (s < cnt) ? g_wts[e][s] : 0.f;
    }
    __syncthreads();

    const int r0 = tid >> 3;
    const int c4 = (tid & 7) * 4;
    const float* ap[4];
    uint32_t asz[4];
#pragma unroll
    for (int i = 0; i < 4; i++) {
        int p = sp[r0 + 32 * i];
        asz[i] = (p >= 0) ? 16u : 0u;
        ap[i] = g_h + (size_t)((p >= 0) ? p : 0) * FF + c4;
    }
    const float* wb = g_wdc + (size_t)e * DD * FF + (size_t)(n0 + r0) * FF + c4;
    const uint32_t rowb = (uint32_t)(r0 * KSTRIDE + c4) * 4u;

    const int lane = tid & 31;
    const int g  = lane >> 2;
    const int tg = lane & 3;
    const int wm = (tid >> 5) & 3;
    const int wn = tid >> 7;

    const int lt = lane >> 3;
    const int tr = lane & 7;
    uint32_t aoff[2];
#pragma unroll
    for (int i = 0; i < 2; i++) {
        int row = wm * 32 + i * 16 + (lt & 1) * 8 + tr;
        aoff[i] = (uint32_t)(row * KSTRIDE + (lt >> 1) * 4) * 4u;
    }
    uint32_t boff[4];
#pragma unroll
    for (int p = 0; p < 4; p++) {
        int row = wn * 64 + p * 16 + (lt >> 1) * 8 + tr;
        boff[p] = (uint32_t)(row * KSTRIDE + (lt & 1) * 4) * 4u;
    }

    float acc[2][8][4];
#pragma unroll
    for (int i = 0; i < 2; i++)
#pragma unroll
        for (int j = 0; j < 8; j++)
#pragma unroll
            for (int q = 0; q < 4; q++) acc[i][j][q] = 0.f;

    const int NC = FF / BK;   // 128

    auto fill = [&](int ch) {
        const uint32_t so = (uint32_t)(ch % 3) * ((uint32_t)ST2 * 4u);
        const int k0 = ch * BK;
        uint32_t sA = sb + so + rowb;
        uint32_t sB = sA + 4608u * 4u;
#pragma unroll
        for (int i = 0; i < 4; i++) {
            CPA16(sA + i * (32u * KSTRIDE * 4u), ap[i] + k0, asz[i]);
            CPA16(sB + i * (32u * KSTRIDE * 4u), wb + (size_t)i * 32 * FF + k0, 16u);
        }
    };

    fill(0); CP_COMMIT();
    fill(1); CP_COMMIT();

    for (int c = 0; c < NC; c++) {
        if (c + 2 < NC) fill(c + 2);
        CP_COMMIT();
        CP_WAIT2();
        __syncthreads();

        const uint32_t stg = sb + (uint32_t)(c % 3) * ((uint32_t)ST2 * 4u);
        const uint32_t sB  = stg + 4608u * 4u;

#pragma unroll
        for (int s = 0; s < 4; s++) {
            const uint32_t kb = (uint32_t)s * 32u;
            uint32_t af[2][4];
            LDSM4(af[0][0], af[0][1], af[0][2], af[0][3], stg + aoff[0] + kb);
            LDSM4(af[1][0], af[1][1], af[1][2], af[1][3], stg + aoff[1] + kb);
#pragma unroll
            for (int p = 0; p < 4; p++) {
                uint32_t b0, b1, b2, b3;
                LDSM4(b0, b1, b2, b3, sB + boff[p] + kb);
                const int j0 = p * 2, j1 = p * 2 + 1;
                MMA_TF32(acc[0][j0], af[0][0], af[0][1], af[0][2], af[0][3], b0, b1);
                MMA_TF32(acc[1][j0], af[1][0], af[1][1], af[1][2], af[1][3], b0, b1);
                MMA_TF32(acc[0][j1], af[0][0], af[0][1], af[0][2], af[0][3], b2, b3);
                MMA_TF32(acc[1][j1], af[1][0], af[1][1], af[1][2], af[1][3], b2, b3);
            }
        }
        __syncthreads();
    }

    // epilogue: g_o[pair] = acc * w  (plain stores; combine kernel sums)
#pragma unroll
    for (int i = 0; i < 2; i++) {
#pragma unroll
        for (int half = 0; half < 2; half++) {
            const int rl = wm * 32 + i * 16 + g + half * 8;
            const int pr = sp[rl];
            if (pr < 0) continue;
            const float w = sw[rl];
            float* orow = g_o + (size_t)pr * DD + n0 + wn * 64 + 2 * tg;
#pragma unroll
            for (int j = 0; j < 8; j++) {
                float2 ov;
                ov.x = acc[i][j][half * 2 + 0] * w;
                ov.y = acc[i][j][half * 2 + 1] * w;
                *(float2*)(orow + j * 8) = ov;
            }
        }
    }
}

// ---------------- combine: out[t] = g_o[2t] + g_o[2t+1] ----------------
__global__ void combine_kernel(float4* __restrict__ out) {
    int i = blockIdx.x * blockDim.x + threadIdx.x;   // over NT*DD/4
    if (i >= NT * DD / 4) return;
    const int t  = i / (DD / 4);
    const int d4 = i % (DD / 4);
    const float4* a = (const float4*)(g_o + (size_t)(2 * t) * DD) + d4;
    const float4* b = (const float4*)(g_o + (size_t)(2 * t + 1) * DD) + d4;
    float4 va = *a, vb = *b;
    va.x += vb.x; va.y += vb.y; va.z += vb.z; va.w += vb.w;
    out[i] = va;
}

// ---------------------------------------------------------------------------
extern "C" void kernel_launch(void* const* d_in, const int* in_sizes, int n_in,
                              void* d_out, int out_size) {
    const float* x     = (const float*)d_in[0];
    const float* Wgate = (const float*)d_in[1];
    const float* Wg    = (const float*)d_in[2];
    const float* Wu    = (const float*)d_in[3];
    const float* Wd    = (const float*)d_in[4];
    float* out = (float*)d_out;

    cudaFuncSetAttribute(ffn1_mma, cudaFuncAttributeMaxDynamicSharedMemorySize, SMEM1_BYTES);
    cudaFuncSetAttribute(ffn2_mma, cudaFuncAttributeMaxDynamicSharedMemorySize, SMEM2_BYTES);

    // tf32 pre-round copies
    float *g_xc_p, *g_wgc_p, *g_wuc_p, *g_wdc_p;
    cudaGetSymbolAddress((void**)&g_xc_p,  g_xc);
    cudaGetSymbolAddress((void**)&g_wgc_p, g_wgc);
    cudaGetSymbolAddress((void**)&g_wuc_p, g_wuc);
    cudaGetSymbolAddress((void**)&g_wdc_p, g_wdc);

    const int n4x = NT * DD / 4;
    const int n4w = NE * FF * DD / 4;
    cvt_kernel<<<(n4x + 255) / 256, 256>>>((const float4*)x,  (float4*)g_xc_p,  n4x);
    cvt_kernel<<<(n4w + 255) / 256, 256>>>((const float4*)Wg, (float4*)g_wgc_p, n4w);
    cvt_kernel<<<(n4w + 255) / 256, 256>>>((const float4*)Wu, (float4*)g_wuc_p, n4w);
    cvt_kernel<<<(n4w + 255) / 256, 256>>>((const float4*)Wd, (float4*)g_wdc_p, n4w);

    zero_counts_kernel<<<1, 32>>>();
    router_kernel<<<NT / 8, 256>>>(x, Wgate);

    dim3 g1(NT / BM, FF / BN, NE);
    ffn1_mma<<<g1, 256, SMEM1_BYTES>>>();

    dim3 g2(NT / BM, DD / BN, NE);
    ffn2_mma<<<g2, 256, SMEM2_BYTES>>>();

    combine_kernel<<<(NT * DD / 4 + 255) / 256, 256>>>((float4*)out);
}